// round 1
// baseline (speedup 1.0000x reference)
#include <cuda_runtime.h>
#include <cuda_bf16.h>

#define DIM 128
#define NPROJ 256
#define TOK_PER_CTA 64
#define THREADS 512

// sqrt(pi/2) / 256
#define DEQUANT_SCALE 0.0048957583488887505f

// Scratch for transposed S: St[d][p] = S[p][d]  (128 x 256 floats = 128KB)
__device__ float g_St[DIM * NPROJ];

// ---------------------------------------------------------------------------
// Kernel 1: transpose S (tiny, one-time per launch)
// ---------------------------------------------------------------------------
__global__ void qjl_transpose_S(const float* __restrict__ S) {
    int d = blockIdx.x;   // 0..127
    int p = threadIdx.x;  // 0..255
    g_St[d * NPROJ + p] = S[p * DIM + d];
}

// ---------------------------------------------------------------------------
// Kernel 2: fused QJL estimate.
//   CTA: 64 tokens. 16 warps, warp -> 4 tokens. lane -> 8 projections
//   (two contiguous float4 blocks: p = lane*4..lane*4+3 and 128+lane*4..+3).
//   smem: St[128][256] (128KB) + q[64][128] (32KB) + k[64][128] (32KB).
// ---------------------------------------------------------------------------
__global__ void __launch_bounds__(THREADS, 1)
qjl_main_kernel(const float* __restrict__ q_g,
                const float* __restrict__ k_g,
                float* __restrict__ out,
                int ntok) {
    extern __shared__ float smem[];
    float* St = smem;                          // DIM*NPROJ floats
    float* qs = smem + DIM * NPROJ;            // TOK_PER_CTA*DIM
    float* ks = qs + TOK_PER_CTA * DIM;        // TOK_PER_CTA*DIM

    const int tid = threadIdx.x;
    const int cta_tok = blockIdx.x * TOK_PER_CTA;

    // ---- stage St (coalesced float4 copy from global scratch) ----
    {
        float4* dst = reinterpret_cast<float4*>(St);
        const float4* src = reinterpret_cast<const float4*>(g_St);
        #pragma unroll
        for (int i = 0; i < (DIM * NPROJ / 4) / THREADS; i++)
            dst[tid + i * THREADS] = src[tid + i * THREADS];
    }

    // ---- stage q,k token tiles (contiguous, coalesced) ----
    {
        const float4* qg = reinterpret_cast<const float4*>(q_g) + (size_t)cta_tok * (DIM / 4);
        const float4* kg = reinterpret_cast<const float4*>(k_g) + (size_t)cta_tok * (DIM / 4);
        float4* qd4 = reinterpret_cast<float4*>(qs);
        float4* kd4 = reinterpret_cast<float4*>(ks);
        int limit = (ntok - cta_tok) * (DIM / 4);
        if (limit > TOK_PER_CTA * (DIM / 4)) limit = TOK_PER_CTA * (DIM / 4);
        #pragma unroll
        for (int i = 0; i < TOK_PER_CTA * (DIM / 4) / THREADS; i++) {
            int v = tid + i * THREADS;
            if (v < limit) { qd4[v] = qg[v]; kd4[v] = kg[v]; }
        }
    }
    __syncthreads();

    const int w = tid >> 5;   // warp 0..15 -> tokens w*4 .. w*4+3
    const int l = tid & 31;   // lane -> projections

    const float* qw = qs + (w * 4) * DIM;
    const float* kw = ks + (w * 4) * DIM;
    const float4* St4 = reinterpret_cast<const float4*>(St);  // row = 64 float4

    // accumulators: [token j][p sub], for low (p<128) and high (p>=128) blocks
    float aK0[4][4], aK1[4][4], aQ0[4][4], aQ1[4][4];
    #pragma unroll
    for (int j = 0; j < 4; j++)
        #pragma unroll
        for (int i = 0; i < 4; i++) {
            aK0[j][i] = 0.f; aK1[j][i] = 0.f;
            aQ0[j][i] = 0.f; aQ1[j][i] = 0.f;
        }

    #pragma unroll 4
    for (int d = 0; d < DIM; d++) {
        float4 s0 = St4[d * (NPROJ / 4) + l];            // St[d][l*4 ..]
        float4 s1 = St4[d * (NPROJ / 4) + 32 + l];       // St[d][128+l*4 ..]
        #pragma unroll
        for (int j = 0; j < 4; j++) {
            float kd = kw[j * DIM + d];
            float qd = qw[j * DIM + d];
            aK0[j][0] += kd * s0.x;  aK0[j][1] += kd * s0.y;
            aK0[j][2] += kd * s0.z;  aK0[j][3] += kd * s0.w;
            aK1[j][0] += kd * s1.x;  aK1[j][1] += kd * s1.y;
            aK1[j][2] += kd * s1.z;  aK1[j][3] += kd * s1.w;
            aQ0[j][0] += qd * s0.x;  aQ0[j][1] += qd * s0.y;
            aQ0[j][2] += qd * s0.z;  aQ0[j][3] += qd * s0.w;
            aQ1[j][0] += qd * s1.x;  aQ1[j][1] += qd * s1.y;
            aQ1[j][2] += qd * s1.z;  aQ1[j][3] += qd * s1.w;
        }
    }

    // ---- epilogue: sign-select, reduce over p (lanes), write ----
    #pragma unroll
    for (int j = 0; j < 4; j++) {
        float e = 0.f;
        #pragma unroll
        for (int i = 0; i < 4; i++) {
            e += (aK0[j][i] > 0.f) ? aQ0[j][i] : -aQ0[j][i];
            e += (aK1[j][i] > 0.f) ? aQ1[j][i] : -aQ1[j][i];
        }
        #pragma unroll
        for (int off = 16; off > 0; off >>= 1)
            e += __shfl_xor_sync(0xFFFFFFFFu, e, off);
        int tok = cta_tok + w * 4 + j;
        if (l == 0 && tok < ntok)
            out[tok] = DEQUANT_SCALE * e;
    }
}

// ---------------------------------------------------------------------------
extern "C" void kernel_launch(void* const* d_in, const int* in_sizes, int n_in,
                              void* d_out, int out_size) {
    const float* q = (const float*)d_in[0];
    const float* k = (const float*)d_in[1];
    const float* S = (const float*)d_in[2];
    float* out = (float*)d_out;

    int ntok = in_sizes[0] / DIM;

    // one-time S transpose into device scratch
    qjl_transpose_S<<<DIM, NPROJ>>>(S);

    size_t smem_bytes = (size_t)(DIM * NPROJ + 2 * TOK_PER_CTA * DIM) * sizeof(float); // 192KB
    cudaFuncSetAttribute(qjl_main_kernel,
                         cudaFuncAttributeMaxDynamicSharedMemorySize,
                         (int)smem_bytes);

    int grid = (ntok + TOK_PER_CTA - 1) / TOK_PER_CTA;
    qjl_main_kernel<<<grid, THREADS, smem_bytes>>>(q, k, out, ntok);
}

// round 3
// speedup vs baseline: 1.6644x; 1.6644x over previous
#include <cuda_runtime.h>
#include <cuda_fp16.h>
#include <cstdint>

#define THREADS 512
#define SCALE 0.0048957583488887505f   // sqrt(pi/2)/256
#define TAU 1e-4f

// smem layout (bytes). Row pitch 272B = 136 halves (conflict-free ldmatrix).
#define EST4_OFF 0                     // float[128][4]
#define KHI_OFF  2048                  // 128 x 272
#define KLO_OFF  (KHI_OFF + 34816)     // 128 x 272   (reused for q_hi)
#define SHI_OFF  (KLO_OFF + 34816)     // 256 x 272
#define SLO_OFF  (SHI_OFF + 69632)     // 256 x 272
#define SMEM_TOTAL (SLO_OFF + 69632)   // 210944

__device__ __forceinline__ uint32_t smem_u32(const void* p) {
    uint32_t a;
    asm("{ .reg .u64 t; cvta.to.shared.u64 t, %1; cvt.u32.u64 %0, t; }"
        : "=r"(a) : "l"(p));
    return a;
}

__device__ __forceinline__ void ldsm_x4(uint32_t* r, uint32_t a) {
    asm volatile("ldmatrix.sync.aligned.m8n8.x4.shared.b16 {%0,%1,%2,%3}, [%4];"
                 : "=r"(r[0]), "=r"(r[1]), "=r"(r[2]), "=r"(r[3]) : "r"(a));
}
__device__ __forceinline__ void ldsm_x2(uint32_t& r0, uint32_t& r1, uint32_t a) {
    asm volatile("ldmatrix.sync.aligned.m8n8.x2.shared.b16 {%0,%1}, [%2];"
                 : "=r"(r0), "=r"(r1) : "r"(a));
}
__device__ __forceinline__ void mma16816(float* d, const uint32_t* a,
                                         uint32_t b0, uint32_t b1) {
    asm volatile(
        "mma.sync.aligned.m16n8k16.row.col.f32.f16.f16.f32 "
        "{%0,%1,%2,%3}, {%4,%5,%6,%7}, {%8,%9}, {%0,%1,%2,%3};"
        : "+f"(d[0]), "+f"(d[1]), "+f"(d[2]), "+f"(d[3])
        : "r"(a[0]), "r"(a[1]), "r"(a[2]), "r"(a[3]), "r"(b0), "r"(b1));
}

// one GEMM pass: acc[2][8][4] += A(128x128 fp16, warp rows) * B(256x128 fp16)^T
__device__ __forceinline__ void gemm_pass(uint32_t sb, uint32_t Abase, uint32_t Bbase,
                                          uint32_t a_off, uint32_t b_off,
                                          float (&acc)[2][8][4]) {
    #pragma unroll
    for (int ks = 0; ks < 8; ks++) {
        uint32_t aaddr = sb + Abase + a_off + ks * 32;
        uint32_t A0[4], A1[4];
        ldsm_x4(A0, aaddr);
        ldsm_x4(A1, aaddr + 16 * 272);
        #pragma unroll
        for (int nt = 0; nt < 8; nt++) {
            uint32_t b0, b1;
            ldsm_x2(b0, b1, sb + Bbase + b_off + nt * (8 * 272) + ks * 32);
            mma16816(acc[0][nt], A0, b0, b1);
            mma16816(acc[1][nt], A1, b0, b1);
        }
    }
}

__device__ __forceinline__ void split_store(char* base, uint32_t off_hi, uint32_t off_lo,
                                            int row, int c4, float4 v) {
    __half hx = __float2half_rn(v.x), hy = __float2half_rn(v.y);
    __half hz = __float2half_rn(v.z), hw = __float2half_rn(v.w);
    __half lx = __float2half_rn(v.x - __half2float(hx));
    __half ly = __float2half_rn(v.y - __half2float(hy));
    __half lz = __float2half_rn(v.z - __half2float(hz));
    __half lw = __float2half_rn(v.w - __half2float(hw));
    __half2* dh = (__half2*)(base + off_hi + row * 272 + c4 * 8);
    __half2* dl = (__half2*)(base + off_lo + row * 272 + c4 * 8);
    dh[0] = __halves2half2(hx, hy); dh[1] = __halves2half2(hz, hw);
    dl[0] = __halves2half2(lx, ly); dl[1] = __halves2half2(lz, lw);
}

__global__ void __launch_bounds__(THREADS, 1)
qjl_fused(const float* __restrict__ qry, const float* __restrict__ key,
          const float* __restrict__ Sg, float* __restrict__ out, int ntok) {
    extern __shared__ char smem[];
    const uint32_t sb = smem_u32(smem);
    const int tid = threadIdx.x, wid = tid >> 5, l = tid & 31;
    const int tok_base = blockIdx.x * 128;

    // ---- stage key hi/lo [128 tok x 128 d] ----
    for (int u = tid; u < 4096; u += THREADS) {
        int row = u >> 5, c4 = u & 31;
        int tok = tok_base + row; if (tok >= ntok) tok = ntok - 1;
        float4 v = __ldg((const float4*)(key + (size_t)tok * 128) + c4);
        split_store(smem, KHI_OFF, KLO_OFF, row, c4, v);
    }
    // ---- stage S hi/lo [256 p x 128 d] ----
    for (int u = tid; u < 8192; u += THREADS) {
        int row = u >> 5, c4 = u & 31;
        float4 v = __ldg((const float4*)(Sg + (size_t)row * 128) + c4);
        split_store(smem, SHI_OFF, SLO_OFF, row, c4, v);
    }
    __syncthreads();

    // lane/warp fragment offsets (bytes)
    const uint32_t a_off = (uint32_t)(wid >> 2) * (32 * 272)
                         + (uint32_t)(l & 15) * 272 + (uint32_t)(l >> 4) * 16;
    const uint32_t b_off = (uint32_t)(wid & 3) * (64 * 272)
                         + (uint32_t)(l & 7) * 272 + (uint32_t)((l >> 3) & 1) * 16;

    float acc[2][8][4];
    #pragma unroll
    for (int mt = 0; mt < 2; mt++)
        #pragma unroll
        for (int nt = 0; nt < 8; nt++)
            #pragma unroll
            for (int j = 0; j < 4; j++) acc[mt][nt][j] = 0.f;

    // ---- k-projection: 3 split passes (hi*hi + hi*lo + lo*hi) ----
    gemm_pass(sb, KHI_OFF, SHI_OFF, a_off, b_off, acc);
    gemm_pass(sb, KHI_OFF, SLO_OFF, a_off, b_off, acc);
    gemm_pass(sb, KLO_OFF, SHI_OFF, a_off, b_off, acc);

    // ---- signs (+ exact fp32 fixup for |proj| < TAU) ----
    uint32_t m0 = 0, m1 = 0;
    #pragma unroll
    for (int mt = 0; mt < 2; mt++)
        #pragma unroll
        for (int nt = 0; nt < 8; nt++)
            #pragma unroll
            for (int j = 0; j < 4; j++) {
                float v = acc[mt][nt][j];
                if (fabsf(v) < TAU) {
                    int row = (wid >> 2) * 32 + mt * 16 + (l >> 2) + (j >> 1) * 8;
                    int tok = tok_base + row; if (tok >= ntok) tok = ntok - 1;
                    int proj = (wid & 3) * 64 + nt * 8 + (l & 3) * 2 + (j & 1);
                    const float* kr = key + (size_t)tok * 128;
                    const float* sr = Sg + (size_t)proj * 128;
                    float ex = 0.f;
                    for (int d = 0; d < 128; d++) ex = fmaf(__ldg(kr + d), __ldg(sr + d), ex);
                    v = ex;
                }
                int id = mt * 32 + nt * 4 + j;
                uint32_t bit = (v > 0.f) ? 1u : 0u;
                if (id < 32) m0 |= bit << id; else m1 |= bit << (id - 32);
            }

    __syncthreads();   // all warps done reading KLO (pass 3)

    // ---- stage q hi into KLO buffer ----
    for (int u = tid; u < 4096; u += THREADS) {
        int row = u >> 5, c4 = u & 31;
        int tok = tok_base + row; if (tok >= ntok) tok = ntok - 1;
        float4 v = __ldg((const float4*)(qry + (size_t)tok * 128) + c4);
        __half2* dh = (__half2*)(smem + KLO_OFF + row * 272 + c4 * 8);
        dh[0] = __halves2half2(__float2half_rn(v.x), __float2half_rn(v.y));
        dh[1] = __halves2half2(__float2half_rn(v.z), __float2half_rn(v.w));
    }
    __syncthreads();

    // ---- q-projection: single fp16 pass ----
    #pragma unroll
    for (int mt = 0; mt < 2; mt++)
        #pragma unroll
        for (int nt = 0; nt < 8; nt++)
            #pragma unroll
            for (int j = 0; j < 4; j++) acc[mt][nt][j] = 0.f;
    gemm_pass(sb, KLO_OFF, SHI_OFF, a_off, b_off, acc);

    // ---- epilogue: signed reduction over p, deterministic ----
    float* est4 = (float*)smem;   // [128][4]
    #pragma unroll
    for (int mt = 0; mt < 2; mt++)
        #pragma unroll
        for (int h = 0; h < 2; h++) {
            float s = 0.f;
            #pragma unroll
            for (int nt = 0; nt < 8; nt++)
                #pragma unroll
                for (int jj = 0; jj < 2; jj++) {
                    int j = h * 2 + jj;
                    int id = mt * 32 + nt * 4 + j;
                    uint32_t bit = ((id < 32) ? (m0 >> id) : (m1 >> (id - 32))) & 1u;
                    float v = acc[mt][nt][j];
                    s += bit ? v : -v;
                }
            s += __shfl_xor_sync(0xFFFFFFFFu, s, 1);
            s += __shfl_xor_sync(0xFFFFFFFFu, s, 2);
            if ((l & 3) == 0) {
                int row = (wid >> 2) * 32 + mt * 16 + h * 8 + (l >> 2);
                est4[row * 4 + (wid & 3)] = s;
            }
        }
    __syncthreads();
    if (tid < 128) {
        int tok = tok_base + tid;
        if (tok < ntok) {
            float e = (est4[tid * 4 + 0] + est4[tid * 4 + 1])
                    + (est4[tid * 4 + 2] + est4[tid * 4 + 3]);
            out[tok] = SCALE * e;
        }
    }
}

extern "C" void kernel_launch(void* const* d_in, const int* in_sizes, int n_in,
                              void* d_out, int out_size) {
    const float* q = (const float*)d_in[0];
    const float* k = (const float*)d_in[1];
    const float* S = (const float*)d_in[2];
    float* out = (float*)d_out;

    int ntok = in_sizes[0] / 128;
    int ntiles = (ntok + 127) / 128;

    cudaFuncSetAttribute(qjl_fused, cudaFuncAttributeMaxDynamicSharedMemorySize,
                         SMEM_TOTAL);
    qjl_fused<<<ntiles, THREADS, SMEM_TOTAL>>>(q, k, S, out, ntok);
}